// round 1
// baseline (speedup 1.0000x reference)
#include <cuda_runtime.h>
#include <cstdint>

// Problem constants (fixed shapes per reference)
#define DIMC 128
#define KC   65536
#define BC   1024
#define LC   512
#define PC   8388608

// Scratch (device globals — no allocation allowed)
__device__ float g_queueT[(size_t)KC * DIMC];   // 32 MB transposed queue [K, DIM]
__device__ float g_qn[BC * DIMC];               // normalized q
__device__ float g_keysN[BC * DIMC];            // normalized keys

// ---------------------------------------------------------------------------
// K0: row-normalize q and keys (one warp per row, float4 per lane)
// ---------------------------------------------------------------------------
__global__ void normalize_rows_kernel(const float* __restrict__ q,
                                      const float* __restrict__ keys) {
    int gw   = (blockIdx.x * blockDim.x + threadIdx.x) >> 5;  // global warp id, 0..2047
    int lane = threadIdx.x & 31;
    const float* src;
    float* dst;
    if (gw < BC) { src = q    + (size_t)gw * DIMC;        dst = g_qn    + (size_t)gw * DIMC; }
    else         { src = keys + (size_t)(gw - BC) * DIMC; dst = g_keysN + (size_t)(gw - BC) * DIMC; }

    float4 v = reinterpret_cast<const float4*>(src)[lane];
    float s = v.x * v.x + v.y * v.y + v.z * v.z + v.w * v.w;
    #pragma unroll
    for (int o = 16; o > 0; o >>= 1) s += __shfl_xor_sync(0xFFFFFFFFu, s, o);
    float inv = 1.0f / sqrtf(s);
    float4 r = make_float4(v.x * inv, v.y * inv, v.z * inv, v.w * inv);
    reinterpret_cast<float4*>(dst)[lane] = r;
}

// ---------------------------------------------------------------------------
// K1: transpose queue [DIM, K] -> g_queueT [K, DIM]   (tiled 32x32)
// ---------------------------------------------------------------------------
__global__ void transpose_kernel(const float* __restrict__ queue) {
    __shared__ float tile[32][33];
    int k0 = blockIdx.x * 32;
    int d0 = blockIdx.y * 32;
    int tx = threadIdx.x, ty = threadIdx.y;   // block (32, 8)
    #pragma unroll
    for (int j = 0; j < 32; j += 8)
        tile[ty + j][tx] = queue[(size_t)(d0 + ty + j) * KC + (k0 + tx)];
    __syncthreads();
    #pragma unroll
    for (int j = 0; j < 32; j += 8)
        g_queueT[(size_t)(k0 + ty + j) * DIMC + (d0 + tx)] = tile[tx][ty + j];
}

// ---------------------------------------------------------------------------
// K2a: new_param_k = 0.7*param_k + 0.3*param_q ; also zero labels
// ---------------------------------------------------------------------------
__global__ void param_labels_kernel(const float* __restrict__ pq,
                                    const float* __restrict__ pk,
                                    float* __restrict__ out_pk,
                                    float* __restrict__ labels) {
    int i = blockIdx.x * blockDim.x + threadIdx.x;   // over P/4 float4s
    float4 a = reinterpret_cast<const float4*>(pq)[i];
    float4 b = reinterpret_cast<const float4*>(pk)[i];
    float4 r = make_float4(b.x * 0.7f + a.x * 0.3f,
                           b.y * 0.7f + a.y * 0.3f,
                           b.z * 0.7f + a.z * 0.3f,
                           b.w * 0.7f + a.w * 0.3f);
    reinterpret_cast<float4*>(out_pk)[i] = r;
    if (i < BC / 4)
        reinterpret_cast<float4*>(labels)[i] = make_float4(0.f, 0.f, 0.f, 0.f);
}

// ---------------------------------------------------------------------------
// K2b: new_queue = queue with columns [ptr, ptr+B) replaced by keysN^T
// ---------------------------------------------------------------------------
__global__ void queue_out_kernel(const float* __restrict__ queue,
                                 float* __restrict__ outq,
                                 const int* __restrict__ ptrp) {
    int i = blockIdx.x * blockDim.x + threadIdx.x;   // over (DIM*K)/4 float4s
    int ptr = *ptrp;
    float4 v = reinterpret_cast<const float4*>(queue)[i];
    int e = i << 2;
    int d = e >> 16;        // / K (K = 65536)
    int k = e & (KC - 1);   // % K
    float* c = &v.x;
    #pragma unroll
    for (int j = 0; j < 4; ++j) {
        int r = k + j - ptr;
        if ((unsigned)r < (unsigned)BC)
            c[j] = g_keysN[(size_t)r * DIMC + d];
    }
    reinterpret_cast<float4*>(outq)[i] = v;
}

// ---------------------------------------------------------------------------
// K3: logits[b,l] = dot(queueT[idx[b,l]], qn[b]) / 0.09
//     block per b; 8 warps; warp computes one sample per step (2-way unrolled)
// ---------------------------------------------------------------------------
__global__ void logits_kernel(const int* __restrict__ sidx,
                              float* __restrict__ logits) {
    int b = blockIdx.x;
    __shared__ float qs[DIMC];
    if (threadIdx.x < DIMC) qs[threadIdx.x] = g_qn[(size_t)b * DIMC + threadIdx.x];
    __syncthreads();

    int lane = threadIdx.x & 31;
    int warp = threadIdx.x >> 5;  // 0..7
    float4 myq = reinterpret_cast<const float4*>(qs)[lane];
    const int* row = sidx + (size_t)b * LC;
    float* lrow = logits + (size_t)b * LC;

    for (int l = warp * 2; l < LC; l += 16) {
        int i0 = row[l];
        int i1 = row[l + 1];
        float4 c0 = reinterpret_cast<const float4*>(g_queueT + (size_t)i0 * DIMC)[lane];
        float4 c1 = reinterpret_cast<const float4*>(g_queueT + (size_t)i1 * DIMC)[lane];
        float s0 = c0.x * myq.x + c0.y * myq.y + c0.z * myq.z + c0.w * myq.w;
        float s1 = c1.x * myq.x + c1.y * myq.y + c1.z * myq.z + c1.w * myq.w;
        #pragma unroll
        for (int o = 16; o > 0; o >>= 1) {
            s0 += __shfl_xor_sync(0xFFFFFFFFu, s0, o);
            s1 += __shfl_xor_sync(0xFFFFFFFFu, s1, o);
        }
        if (lane == 0) {
            lrow[l]     = s0 / 0.09f;
            lrow[l + 1] = s1 / 0.09f;
        }
    }
}

// ---------------------------------------------------------------------------
extern "C" void kernel_launch(void* const* d_in, const int* in_sizes, int n_in,
                              void* d_out, int out_size) {
    const float* q        = (const float*)d_in[0];
    const float* queue    = (const float*)d_in[1];
    const float* keys     = (const float*)d_in[2];
    const float* param_q  = (const float*)d_in[3];
    const float* param_k  = (const float*)d_in[4];
    const int*   sidx     = (const int*)  d_in[5];
    const int*   ptr      = (const int*)  d_in[6];

    float* out       = (float*)d_out;
    float* logits    = out;                            // B*L = 524288
    float* labels    = logits + (size_t)BC * LC;       // 1024
    float* new_queue = labels + BC;                    // DIM*K = 8388608
    float* new_pk    = new_queue + (size_t)DIMC * KC;  // P = 8388608

    // K0: normalize q and keys (2048 warps)
    normalize_rows_kernel<<<256, 256>>>(q, keys);

    // K1: transpose queue -> queueT
    transpose_kernel<<<dim3(KC / 32, DIMC / 32), dim3(32, 8)>>>(queue);

    // K2a: param EMA + labels
    param_labels_kernel<<<PC / 4 / 256, 256>>>(param_q, param_k, new_pk, labels);

    // K2b: queue copy + enqueue
    queue_out_kernel<<<((size_t)DIMC * KC / 4) / 256, 256>>>(queue, new_queue, ptr);

    // K3: sampled logits
    logits_kernel<<<BC, 256>>>(sidx, logits);
}

// round 2
// speedup vs baseline: 1.3962x; 1.3962x over previous
#include <cuda_runtime.h>
#include <cstdint>

// Problem constants (fixed shapes per reference)
#define DIMC 128
#define KC   65536
#define BC   1024
#define LC   512
#define PC   8388608

// Scratch (device global — no allocation allowed)
__device__ float g_queueT[(size_t)KC * DIMC];   // 32 MB transposed queue [K, DIM]

// ---------------------------------------------------------------------------
// Kernel A: per 32x32 tile of queue [DIM, K]:
//   - write transposed original values to g_queueT  (stays in L2 for gather)
//   - write new_queue = queue with columns [ptr,ptr+B) replaced by
//     normalize(keys).T   (key norms computed on the fly)
// grid = 8192 blocks (2048 k-tiles x 4 d-tiles), 256 threads
// ---------------------------------------------------------------------------
__global__ void tile_kernel(const float* __restrict__ queue,
                            const float* __restrict__ keys,
                            float* __restrict__ new_queue,
                            const int* __restrict__ ptrp) {
    __shared__ float tile[32][33];
    __shared__ float skey[32][33];

    int bx = blockIdx.x & 2047;        // k-tile index (0..2047)
    int by = blockIdx.x >> 11;         // d-tile index (0..3)
    int k0 = bx << 5;
    int d0 = by << 5;
    int tx = threadIdx.x & 31;
    int wy = threadIdx.x >> 5;         // warp id 0..7
    int ptr = *ptrp;

    // load tile: tile[d_local][k_local]
    #pragma unroll
    for (int j = 0; j < 32; j += 8)
        tile[wy + j][tx] = __ldcs(&queue[(size_t)(d0 + wy + j) * KC + (k0 + tx)]);
    __syncthreads();

    // transposed write of ORIGINAL values (logits uses the pre-update queue)
    #pragma unroll
    for (int j = 0; j < 32; j += 8)
        g_queueT[(size_t)(k0 + wy + j) * DIMC + (d0 + tx)] = tile[tx][wy + j];

    // on-the-fly normalization of key rows for replaced columns in this tile
    int lo = ptr - k0;          if (lo < 0)  lo = 0;
    int hi = ptr + BC - k0;     if (hi > 32) hi = 32;
    if (lo < hi) {
        #pragma unroll
        for (int cc = 0; cc < 4; ++cc) {
            int c = wy + (cc << 3);                 // column within tile
            if (c >= lo && c < hi) {
                int r = k0 + c - ptr;               // key row
                float4 v = reinterpret_cast<const float4*>(keys + (size_t)r * DIMC)[tx];
                float s = v.x * v.x + v.y * v.y + v.z * v.z + v.w * v.w;
                #pragma unroll
                for (int o = 16; o > 0; o >>= 1) s += __shfl_xor_sync(0xFFFFFFFFu, s, o);
                float inv = 1.0f / sqrtf(s);
                int dd = (tx << 2) - d0;            // local d offset for this lane's chunk
                if (dd >= 0 && dd < 32) {
                    skey[c][dd + 0] = v.x * inv;
                    skey[c][dd + 1] = v.y * inv;
                    skey[c][dd + 2] = v.z * inv;
                    skey[c][dd + 3] = v.w * inv;
                }
            }
        }
        __syncthreads();
    }

    // write new_queue (streamed, don't pollute L2)
    unsigned rcol = (unsigned)(k0 + tx - ptr);      // replaced if < BC
    #pragma unroll
    for (int j = 0; j < 32; j += 8) {
        float val = tile[wy + j][tx];
        if (rcol < (unsigned)BC) val = skey[tx][wy + j];
        __stcs(&new_queue[(size_t)(d0 + wy + j) * KC + (k0 + tx)], val);
    }
}

// ---------------------------------------------------------------------------
// Kernel B: fused logits gather (+inline q normalize, +labels) and param EMA.
//   blocks [0, B)          : logits for batch b (L2-resident gather on queueT)
//   blocks [B, B + P/1024) : EMA stream (ldcs/stcs, bypass-ish L2 policy)
// ---------------------------------------------------------------------------
__global__ void logits_ema_kernel(const float* __restrict__ q,
                                  const int* __restrict__ sidx,
                                  const float* __restrict__ pq,
                                  const float* __restrict__ pk,
                                  float* __restrict__ logits,
                                  float* __restrict__ labels,
                                  float* __restrict__ new_pk) {
    if (blockIdx.x < BC) {
        int b = blockIdx.x;
        __shared__ float qs[DIMC];
        int tid = threadIdx.x;
        if (tid < 32) {
            float4 v = reinterpret_cast<const float4*>(q + (size_t)b * DIMC)[tid];
            float s = v.x * v.x + v.y * v.y + v.z * v.z + v.w * v.w;
            #pragma unroll
            for (int o = 16; o > 0; o >>= 1) s += __shfl_xor_sync(0xFFFFFFFFu, s, o);
            float inv = 1.0f / sqrtf(s);
            reinterpret_cast<float4*>(qs)[tid] =
                make_float4(v.x * inv, v.y * inv, v.z * inv, v.w * inv);
        }
        if (tid == 0) labels[b] = 0.0f;
        __syncthreads();

        int lane = tid & 31;
        int warp = tid >> 5;   // 0..7
        float4 myq = reinterpret_cast<const float4*>(qs)[lane];
        const int* row = sidx + (size_t)b * LC;
        float* lrow = logits + (size_t)b * LC;

        #pragma unroll 4
        for (int l = warp * 2; l < LC; l += 16) {
            int i0 = row[l];
            int i1 = row[l + 1];
            float4 c0 = reinterpret_cast<const float4*>(g_queueT + (size_t)i0 * DIMC)[lane];
            float4 c1 = reinterpret_cast<const float4*>(g_queueT + (size_t)i1 * DIMC)[lane];
            float s0 = c0.x * myq.x + c0.y * myq.y + c0.z * myq.z + c0.w * myq.w;
            float s1 = c1.x * myq.x + c1.y * myq.y + c1.z * myq.z + c1.w * myq.w;
            #pragma unroll
            for (int o = 16; o > 0; o >>= 1) {
                s0 += __shfl_xor_sync(0xFFFFFFFFu, s0, o);
                s1 += __shfl_xor_sync(0xFFFFFFFFu, s1, o);
            }
            if (lane == 0) {
                lrow[l]     = s0 * (1.0f / 0.09f);
                lrow[l + 1] = s1 * (1.0f / 0.09f);
            }
        }
    } else {
        // EMA: new_pk = 0.7*pk + 0.3*pq, streamed
        int i = (blockIdx.x - BC) * 256 + threadIdx.x;   // over P/4 float4s
        float4 a = __ldcs(reinterpret_cast<const float4*>(pq) + i);
        float4 b4 = __ldcs(reinterpret_cast<const float4*>(pk) + i);
        float4 r = make_float4(b4.x * 0.7f + a.x * 0.3f,
                               b4.y * 0.7f + a.y * 0.3f,
                               b4.z * 0.7f + a.z * 0.3f,
                               b4.w * 0.7f + a.w * 0.3f);
        __stcs(reinterpret_cast<float4*>(new_pk) + i, r);
    }
}

// ---------------------------------------------------------------------------
extern "C" void kernel_launch(void* const* d_in, const int* in_sizes, int n_in,
                              void* d_out, int out_size) {
    const float* q        = (const float*)d_in[0];
    const float* queue    = (const float*)d_in[1];
    const float* keys     = (const float*)d_in[2];
    const float* param_q  = (const float*)d_in[3];
    const float* param_k  = (const float*)d_in[4];
    const int*   sidx     = (const int*)  d_in[5];
    const int*   ptr      = (const int*)  d_in[6];

    float* out       = (float*)d_out;
    float* logits    = out;                            // B*L = 524288
    float* labels    = logits + (size_t)BC * LC;       // 1024
    float* new_queue = labels + BC;                    // DIM*K = 8388608
    float* new_pk    = new_queue + (size_t)DIMC * KC;  // P = 8388608

    // Kernel A: transpose + enqueue/copy (one read of queue)
    tile_kernel<<<8192, 256>>>(queue, keys, new_queue, ptr);

    // Kernel B: logits gather + q-normalize + labels + param EMA
    logits_ema_kernel<<<BC + PC / 1024, 256>>>(q, sidx, param_q, param_k,
                                               logits, labels, new_pk);
}

// round 3
// speedup vs baseline: 1.7100x; 1.2247x over previous
#include <cuda_runtime.h>
#include <cuda_fp16.h>
#include <cstdint>

// Problem constants (fixed shapes per reference)
#define DIMC 128
#define KC   65536
#define BC   1024
#define LC   512
#define PC   8388608

// Scratch (device globals — no allocation allowed)
__device__ __half g_qTh[(size_t)KC * DIMC];     // 16 MB transposed queue [K, DIM] in fp16

// ---------------------------------------------------------------------------
// Kernel A: per 32x32 tile of queue [DIM, K]:
//   - write fp16 transposed original values to g_qTh (stays in L2 for gather)
//   - write new_queue = queue with columns [ptr,ptr+B) replaced by
//     normalize(keys).T (key norms computed on the fly, fp32 exact)
// grid = 8192 blocks (2048 k-tiles x 4 d-tiles), 256 threads
// ---------------------------------------------------------------------------
__global__ void tile_kernel(const float* __restrict__ queue,
                            const float* __restrict__ keys,
                            float* __restrict__ new_queue,
                            const int* __restrict__ ptrp) {
    __shared__ float tile[32][33];
    __shared__ float skey[32][33];

    int bx = blockIdx.x & 2047;        // k-tile index (0..2047)
    int by = blockIdx.x >> 11;         // d-tile index (0..3)
    int k0 = bx << 5;
    int d0 = by << 5;
    int tx = threadIdx.x & 31;
    int wy = threadIdx.x >> 5;         // warp id 0..7
    int ptr = *ptrp;

    // load tile: tile[d_local][k_local]
    #pragma unroll
    for (int j = 0; j < 32; j += 8)
        tile[wy + j][tx] = __ldcs(&queue[(size_t)(d0 + wy + j) * KC + (k0 + tx)]);
    __syncthreads();

    // transposed fp16 write of ORIGINAL values (logits uses pre-update queue)
    #pragma unroll
    for (int j = 0; j < 32; j += 8)
        g_qTh[(size_t)(k0 + wy + j) * DIMC + (d0 + tx)] = __float2half(tile[tx][wy + j]);

    // on-the-fly normalization of key rows for replaced columns in this tile
    int lo = ptr - k0;          if (lo < 0)  lo = 0;
    int hi = ptr + BC - k0;     if (hi > 32) hi = 32;
    if (lo < hi) {
        #pragma unroll
        for (int cc = 0; cc < 4; ++cc) {
            int c = wy + (cc << 3);                 // column within tile
            if (c >= lo && c < hi) {
                int r = k0 + c - ptr;               // key row
                float4 v = reinterpret_cast<const float4*>(keys + (size_t)r * DIMC)[tx];
                float s = v.x * v.x + v.y * v.y + v.z * v.z + v.w * v.w;
                #pragma unroll
                for (int o = 16; o > 0; o >>= 1) s += __shfl_xor_sync(0xFFFFFFFFu, s, o);
                float inv = 1.0f / sqrtf(s);
                int dd = (tx << 2) - d0;            // local d offset for this lane's chunk
                if (dd >= 0 && dd < 32) {
                    skey[c][dd + 0] = v.x * inv;
                    skey[c][dd + 1] = v.y * inv;
                    skey[c][dd + 2] = v.z * inv;
                    skey[c][dd + 3] = v.w * inv;
                }
            }
        }
        __syncthreads();
    }

    // write new_queue (streamed, don't pollute L2) — fp32 exact pass-through
    unsigned rcol = (unsigned)(k0 + tx - ptr);      // replaced if < BC
    #pragma unroll
    for (int j = 0; j < 32; j += 8) {
        float val = tile[wy + j][tx];
        if (rcol < (unsigned)BC) val = skey[tx][wy + j];
        __stcs(&new_queue[(size_t)(d0 + wy + j) * KC + (k0 + tx)], val);
    }
}

// ---------------------------------------------------------------------------
// Kernel B: fused logits gather (+inline q normalize, +labels) and param EMA.
//   blocks [0, B)          : logits for batch b (fp16 L2-resident gather)
//   blocks [B, B + P/1024) : EMA stream (ldcs/stcs)
// Logits scheme: 16 lanes per sample; lane loads int4 (8 halves), dot in fp32,
// 4-step shuffle reduce within the 16-lane group. Warp = 2 samples per step.
// ---------------------------------------------------------------------------
__global__ void logits_ema_kernel(const float* __restrict__ q,
                                  const int* __restrict__ sidx,
                                  const float* __restrict__ pq,
                                  const float* __restrict__ pk,
                                  float* __restrict__ logits,
                                  float* __restrict__ labels,
                                  float* __restrict__ new_pk) {
    if (blockIdx.x < BC) {
        int b = blockIdx.x;
        __shared__ float4 qs4[32];
        int tid = threadIdx.x;
        if (tid < 32) {
            float4 v = reinterpret_cast<const float4*>(q + (size_t)b * DIMC)[tid];
            float s = v.x * v.x + v.y * v.y + v.z * v.z + v.w * v.w;
            #pragma unroll
            for (int o = 16; o > 0; o >>= 1) s += __shfl_xor_sync(0xFFFFFFFFu, s, o);
            float inv = 1.0f / sqrtf(s);
            qs4[tid] = make_float4(v.x * inv, v.y * inv, v.z * inv, v.w * inv);
        }
        if (tid == 0) labels[b] = 0.0f;
        __syncthreads();

        int lane    = tid & 31;
        int warp    = tid >> 5;      // 0..7
        int half_id = lane >> 4;     // which of the 2 samples this lane serves
        int sub     = lane & 15;     // position within the 16-lane group

        // this lane's 8 q-values (dims sub*8 .. sub*8+7), hoisted to registers
        float4 qa = qs4[sub * 2];
        float4 qb = qs4[sub * 2 + 1];

        const int* row = sidx + (size_t)b * LC;
        float* lrow = logits + (size_t)b * LC;

        #pragma unroll 4
        for (int l = warp * 2; l < LC; l += 16) {
            int idx = row[l + half_id];
            int4 pkt = reinterpret_cast<const int4*>(g_qTh + (size_t)idx * DIMC)[sub];
            float2 f0 = __half22float2(*reinterpret_cast<__half2*>(&pkt.x));
            float2 f1 = __half22float2(*reinterpret_cast<__half2*>(&pkt.y));
            float2 f2 = __half22float2(*reinterpret_cast<__half2*>(&pkt.z));
            float2 f3 = __half22float2(*reinterpret_cast<__half2*>(&pkt.w));
            float s = f0.x * qa.x + f0.y * qa.y + f1.x * qa.z + f1.y * qa.w
                    + f2.x * qb.x + f2.y * qb.y + f3.x * qb.z + f3.y * qb.w;
            #pragma unroll
            for (int o = 8; o > 0; o >>= 1)
                s += __shfl_xor_sync(0xFFFFFFFFu, s, o);
            if (sub == 0)
                lrow[l + half_id] = s * (1.0f / 0.09f);
        }
    } else {
        // EMA: new_pk = 0.7*pk + 0.3*pq, streamed
        int i = (blockIdx.x - BC) * 256 + threadIdx.x;   // over P/4 float4s
        float4 a  = __ldcs(reinterpret_cast<const float4*>(pq) + i);
        float4 b4 = __ldcs(reinterpret_cast<const float4*>(pk) + i);
        float4 r = make_float4(b4.x * 0.7f + a.x * 0.3f,
                               b4.y * 0.7f + a.y * 0.3f,
                               b4.z * 0.7f + a.z * 0.3f,
                               b4.w * 0.7f + a.w * 0.3f);
        __stcs(reinterpret_cast<float4*>(new_pk) + i, r);
    }
}

// ---------------------------------------------------------------------------
extern "C" void kernel_launch(void* const* d_in, const int* in_sizes, int n_in,
                              void* d_out, int out_size) {
    const float* q        = (const float*)d_in[0];
    const float* queue    = (const float*)d_in[1];
    const float* keys     = (const float*)d_in[2];
    const float* param_q  = (const float*)d_in[3];
    const float* param_k  = (const float*)d_in[4];
    const int*   sidx     = (const int*)  d_in[5];
    const int*   ptr      = (const int*)  d_in[6];

    float* out       = (float*)d_out;
    float* logits    = out;                            // B*L = 524288
    float* labels    = logits + (size_t)BC * LC;       // 1024
    float* new_queue = labels + BC;                    // DIM*K = 8388608
    float* new_pk    = new_queue + (size_t)DIMC * KC;  // P = 8388608

    // Kernel A: fp16 transpose + fp32 enqueue/copy (one read of queue)
    tile_kernel<<<8192, 256>>>(queue, keys, new_queue, ptr);

    // Kernel B: logits gather + q-normalize + labels + param EMA
    logits_ema_kernel<<<BC + PC / 1024, 256>>>(q, sidx, param_q, param_k,
                                               logits, labels, new_pk);
}